// round 9
// baseline (speedup 1.0000x reference)
#include <cuda_runtime.h>
#include <cuda_bf16.h>
#include <stdint.h>

// Problem constants (fixed-shape problem)
#define T_ 16
#define N_ 10000
#define F_ 32          // F_IN
#define FH_ 64         // F_H
#define E_ 160000
#define EP_ (E_ + N_)  // edges + self loops
#define R_ (T_ * N_)   // 160000 rows for GEMMs

#define PRE_BLOCKS 148
#define PRE_THREADS 1024

// ---------------- device scratch (no allocations allowed) ----------------
__device__ __align__(256) float g_deg[N_];
__device__ __align__(256) int   g_cnt[N_];
__device__ __align__(256) int   g_rowptr[N_ + 1];
__device__ __align__(256) int   g_cursor[N_];
__device__ __align__(256) int   g_srcs[EP_];
__device__ __align__(256) float g_norm[EP_];
__device__ __align__(256) float g_A1[(size_t)R_ * F_];   // 20MB: S(x); rewritten in-place to H@W2
__device__ int g_bar_count = 0;
__device__ int g_bar_gen   = 0;

// ---------------- f32x2 helpers ----------------
__device__ __forceinline__ void fma2(uint64_t& d, uint64_t a, uint64_t b) {
    asm("fma.rn.f32x2 %0, %1, %2, %0;" : "+l"(d) : "l"(a), "l"(b));
}
__device__ __forceinline__ uint64_t pk(float lo, float hi) {
    uint64_t r; asm("mov.b64 %0, {%1,%2};" : "=l"(r) : "f"(lo), "f"(hi)); return r;
}
__device__ __forceinline__ void upk(uint64_t v, float& lo, float& hi) {
    asm("mov.b64 {%0,%1}, %2;" : "=f"(lo), "=f"(hi) : "l"(v));
}

// ---------------- software grid barrier (all PRE_BLOCKS co-resident) ----------------
__device__ __forceinline__ void gridbar() {
    __syncthreads();
    if (threadIdx.x == 0) {
        int gen = *(volatile int*)&g_bar_gen;
        __threadfence();
        if (atomicAdd(&g_bar_count, 1) == PRE_BLOCKS - 1) {
            g_bar_count = 0;
            __threadfence();
            atomicExch(&g_bar_gen, gen + 1);
        } else {
            while (*(volatile int*)&g_bar_gen == gen) __nanosleep(256);
        }
        __threadfence();
    }
    __syncthreads();
}

// ---------------- fused preprocessing: init + degree + scan + fill ----------------
__global__ __launch_bounds__(PRE_THREADS) void k_pre(const int* __restrict__ ei,
                                                     const float* __restrict__ ew) {
    const int gtid = blockIdx.x * PRE_THREADS + threadIdx.x;
    const int gstride = PRE_BLOCKS * PRE_THREADS;   // 151552

    // ---- phase 0: zero deg/cnt ----
    for (int i = gtid; i < N_; i += gstride) { g_deg[i] = 0.f; g_cnt[i] = 0; }
    gridbar();

    // ---- phase 1: degree + count histogram ----
    for (int i = gtid; i < EP_; i += gstride) {
        int d; float w;
        if (i < E_) { d = ei[E_ + i]; w = ew[i]; }
        else        { d = i - E_;     w = 1.f;   }
        if ((unsigned)d < N_) {
            atomicAdd(&g_deg[d], w);
            atomicAdd(&g_cnt[d], 1);
        }
    }
    gridbar();

    // ---- phase 2: exclusive scan (block 0 only; others park at the barrier) ----
    if (blockIdx.x == 0) {
        __shared__ int warp_sums[32];
        __shared__ int s_carry;
        int tid = threadIdx.x, lane = tid & 31, wid = tid >> 5;
        if (tid == 0) { s_carry = 0; g_rowptr[0] = 0; }
        __syncthreads();
        for (int base = 0; base < N_; base += 1024) {
            int i = base + tid;
            int v = (i < N_) ? g_cnt[i] : 0;
            int x = v;
            #pragma unroll
            for (int o = 1; o < 32; o <<= 1) {
                int y = __shfl_up_sync(0xffffffffu, x, o);
                if (lane >= o) x += y;
            }
            if (lane == 31) warp_sums[wid] = x;
            __syncthreads();
            if (wid == 0) {
                int s = warp_sums[lane];
                #pragma unroll
                for (int o = 1; o < 32; o <<= 1) {
                    int y = __shfl_up_sync(0xffffffffu, s, o);
                    if (lane >= o) s += y;
                }
                warp_sums[lane] = s;
            }
            __syncthreads();
            int incl = x + (wid > 0 ? warp_sums[wid - 1] : 0) + s_carry;
            if (i < N_) {
                g_rowptr[i + 1] = incl;
                g_cursor[i]     = incl - v;
            }
            __syncthreads();
            if (tid == 1023) s_carry = incl;
            __syncthreads();
        }
    }
    gridbar();

    // ---- phase 3: fill CSR buckets ----
    for (int i = gtid; i < EP_; i += gstride) {
        int s, d; float w;
        if (i < E_) { s = ei[i]; d = ei[E_ + i]; w = ew[i]; }
        else        { s = i - E_; d = s;         w = 1.f;   }
        if ((unsigned)s < N_ && (unsigned)d < N_) {
            float degs = g_deg[s], degd = g_deg[d];
            float ds = (degs > 0.f) ? rsqrtf(degs) : 0.f;
            float dd = (degd > 0.f) ? rsqrtf(degd) : 0.f;
            int pos = atomicAdd(&g_cursor[d], 1);
            g_srcs[pos] = s;
            g_norm[pos] = ds * w * dd;
        }
    }
}

// ---------------- aggregation, float4 lanes ----------------
__device__ __forceinline__ float4 fma4(float w, float4 v, float4 a) {
    a.x = fmaf(w, v.x, a.x); a.y = fmaf(w, v.y, a.y);
    a.z = fmaf(w, v.z, a.z); a.w = fmaf(w, v.w, a.w);
    return a;
}

__global__ __launch_bounds__(128) void k_agg_in(const float* __restrict__ in) {
    int warp = (blockIdx.x * blockDim.x + threadIdx.x) >> 5;
    int lane = threadIdx.x & 31;
    if (warp >= N_) return;
    int n = warp, tg = lane >> 3, fq = lane & 7;
    int beg = g_rowptr[n], end = g_rowptr[n + 1];
    const float4* in4 = (const float4*)in;
    const size_t ts = (size_t)N_ * 8;
    float4 acc[4];
    #pragma unroll
    for (int i = 0; i < 4; i++) acc[i] = make_float4(0.f, 0.f, 0.f, 0.f);
    int e = beg;
    for (; e + 1 < end; e += 2) {
        int s0 = g_srcs[e], s1 = g_srcs[e + 1];
        float w0 = g_norm[e], w1 = g_norm[e + 1];
        size_t p0 = (size_t)s0 * 8 + fq, p1 = (size_t)s1 * 8 + fq;
        #pragma unroll
        for (int i = 0; i < 4; i++) {
            int t = tg * 4 + i;
            float4 v0 = __ldg(&in4[(size_t)t * ts + p0]);
            float4 v1 = __ldg(&in4[(size_t)t * ts + p1]);
            acc[i] = fma4(w0, v0, acc[i]);
            acc[i] = fma4(w1, v1, acc[i]);
        }
    }
    if (e < end) {
        int s0 = g_srcs[e]; float w0 = g_norm[e];
        size_t p0 = (size_t)s0 * 8 + fq;
        #pragma unroll
        for (int i = 0; i < 4; i++) {
            int t = tg * 4 + i;
            acc[i] = fma4(w0, __ldg(&in4[(size_t)t * ts + p0]), acc[i]);
        }
    }
    float4* o4 = (float4*)g_A1;
    #pragma unroll
    for (int i = 0; i < 4; i++) {
        int t = tg * 4 + i;
        o4[(size_t)t * ts + (size_t)n * 8 + fq] = acc[i];
    }
}

// agg_out with fused tail-zero: blocks [0, NODE_BLOCKS) do nodes; rest zero the tail.
#define NODE_BLOCKS ((N_ + 3) / 4)
__global__ __launch_bounds__(128) void k_agg_out(const float* __restrict__ bias,
                                                 float* __restrict__ out, int out_size) {
    if (blockIdx.x >= NODE_BLOCKS) {
        int main_elems = T_ * N_ * F_;
        int i = main_elems + (blockIdx.x - NODE_BLOCKS) * 128 + threadIdx.x;
        if (i < out_size) out[i] = 0.f;
        return;
    }
    int warp = (blockIdx.x * blockDim.x + threadIdx.x) >> 5;
    int lane = threadIdx.x & 31;
    if (warp >= N_) return;
    int n = warp, tg = lane >> 3, fq = lane & 7;
    int beg = g_rowptr[n], end = g_rowptr[n + 1];
    const float4* in4 = (const float4*)g_A1;
    const size_t ts = (size_t)N_ * 8;
    float4 acc[4];
    #pragma unroll
    for (int i = 0; i < 4; i++) acc[i] = make_float4(0.f, 0.f, 0.f, 0.f);
    int e = beg;
    for (; e + 1 < end; e += 2) {
        int s0 = g_srcs[e], s1 = g_srcs[e + 1];
        float w0 = g_norm[e], w1 = g_norm[e + 1];
        size_t p0 = (size_t)s0 * 8 + fq, p1 = (size_t)s1 * 8 + fq;
        #pragma unroll
        for (int i = 0; i < 4; i++) {
            int t = tg * 4 + i;
            float4 v0 = in4[(size_t)t * ts + p0];
            float4 v1 = in4[(size_t)t * ts + p1];
            acc[i] = fma4(w0, v0, acc[i]);
            acc[i] = fma4(w1, v1, acc[i]);
        }
    }
    if (e < end) {
        int s0 = g_srcs[e]; float w0 = g_norm[e];
        size_t p0 = (size_t)s0 * 8 + fq;
        #pragma unroll
        for (int i = 0; i < 4; i++) {
            int t = tg * 4 + i;
            acc[i] = fma4(w0, in4[(size_t)t * ts + p0], acc[i]);
        }
    }
    float4 b = ((const float4*)bias)[fq];
    float4* o4 = (float4*)out;
    #pragma unroll
    for (int i = 0; i < 4; i++) {
        int t = tg * 4 + i;
        float4 v = acc[i];
        v.x += b.x; v.y += b.y; v.z += b.z; v.w += b.w;
        o4[(size_t)t * ts + (size_t)n * 8 + fq] = v;
    }
}

// ---------------- fused GEMM: g_A1 <- relu(g_A1 @ W1 + b1) @ W2  (in-place, 128-row tiles)
__global__ __launch_bounds__(128) void k_gemm_fused(const float* __restrict__ W1,
                                                    const float* __restrict__ b1,
                                                    const float* __restrict__ W2) {
    __shared__ float S[12288];     // 48KB
    float* U   = S;                // [0,4096):  stage1 As k-major; stage2 Wd2
    float* Wd1 = S + 4096;         // [4096,8192): W1 dup (stage1 only)
    float* Hs  = S + 4096;         // [4096,12288): H k-major (after stage1)
    int tid = threadIdx.x;
    int r0 = blockIdx.x * 128;

    // ---- phase 1: load A tile (transpose to k-major, swizzled) + Wd1 ----
    {
        const float4* A4 = (const float4*)(g_A1 + (size_t)r0 * 32);
        #pragma unroll
        for (int it = 0; it < 8; it++) {
            int idx = it * 128 + tid;      // 0..1023
            int row = idx >> 3, c4 = idx & 7;
            float4 v = A4[idx];
            int k0 = c4 * 4;
            int sw = c4 * 4;               // sigmaA(k) = (k>>2)*4
            U[(k0 + 0) * 128 + (row ^ sw)] = v.x;
            U[(k0 + 1) * 128 + (row ^ sw)] = v.y;
            U[(k0 + 2) * 128 + (row ^ sw)] = v.z;
            U[(k0 + 3) * 128 + (row ^ sw)] = v.w;
        }
        #pragma unroll
        for (int it = 0; it < 16; it++) {
            int idx = it * 128 + tid;      // 0..2047
            int k = idx >> 6, c = idx & 63;
            float w = W1[idx];
            int off = k * 128 + (c & 7) * 16 + (c >> 3) * 2;
            Wd1[off] = w; Wd1[off + 1] = w;
        }
    }
    __syncthreads();

    // ---- stage 1: H(128x64) = A(128x32) @ W1(32x64) ----
    int rg = tid >> 3, cg = tid & 7;
    uint64_t acc[4][8];
    #pragma unroll
    for (int p = 0; p < 4; p++)
        #pragma unroll
        for (int j = 0; j < 8; j++) acc[p][j] = 0ull;

    #pragma unroll
    for (int k = 0; k < 32; k++) {
        int sw = (k >> 2) * 4;
        uint64_t a2[4], b2[8];
        #pragma unroll
        for (int p = 0; p < 4; p++)
            a2[p] = *(const uint64_t*)&U[k * 128 + ((rg * 8 + 2 * p) ^ sw)];
        #pragma unroll
        for (int j = 0; j < 8; j++)
            b2[j] = *(const uint64_t*)&Wd1[k * 128 + j * 16 + cg * 2];
        #pragma unroll
        for (int p = 0; p < 4; p++)
            #pragma unroll
            for (int j = 0; j < 8; j++)
                fma2(acc[p][j], a2[p], b2[j]);
    }
    __syncthreads();

    // ---- phase 3: load Wd2 into U; write H (bias+relu) to Hs ----
    #pragma unroll
    for (int it = 0; it < 16; it++) {
        int idx = it * 128 + tid;
        int k = idx >> 5, c = idx & 31;
        float w = W2[idx];
        int off = k * 64 + (c & 3) * 16 + (c >> 2) * 2;
        U[off] = w; U[off + 1] = w;
    }
    {
        int q = cg;
        int sh = (q & 3) * 4 + (q >> 2) * 2;
        #pragma unroll
        for (int j = 0; j < 8; j++) {
            int c = cg * 8 + j;
            float bc = b1[c];
            #pragma unroll
            for (int p = 0; p < 4; p++) {
                float lo, hi; upk(acc[p][j], lo, hi);
                lo = fmaxf(lo + bc, 0.f);
                hi = fmaxf(hi + bc, 0.f);
                *(uint64_t*)&Hs[c * 128 + ((rg * 8 + 2 * p) ^ sh)] = pk(lo, hi);
            }
        }
    }
    __syncthreads();

    // ---- stage 2: Out(128x32) = H(128x64) @ W2(64x32) ----
    uint64_t acc2[4][4];
    #pragma unroll
    for (int p = 0; p < 4; p++)
        #pragma unroll
        for (int j = 0; j < 4; j++) acc2[p][j] = 0ull;

    #pragma unroll
    for (int k = 0; k < 64; k++) {
        int q = k >> 3;
        int sh = (q & 3) * 4 + (q >> 2) * 2;
        uint64_t a2[4], b2[4];
        #pragma unroll
        for (int p = 0; p < 4; p++)
            a2[p] = *(const uint64_t*)&Hs[k * 128 + ((rg * 8 + 2 * p) ^ sh)];
        #pragma unroll
        for (int j = 0; j < 4; j++)
            b2[j] = *(const uint64_t*)&U[k * 64 + j * 16 + cg * 2];
        #pragma unroll
        for (int p = 0; p < 4; p++)
            #pragma unroll
            for (int j = 0; j < 4; j++)
                fma2(acc2[p][j], a2[p], b2[j]);
    }

    // ---- epilogue: write back in-place ----
    #pragma unroll
    for (int p = 0; p < 4; p++) {
        float lo0, hi0, lo1, hi1, lo2, hi2, lo3, hi3;
        upk(acc2[p][0], lo0, hi0);
        upk(acc2[p][1], lo1, hi1);
        upk(acc2[p][2], lo2, hi2);
        upk(acc2[p][3], lo3, hi3);
        int row = r0 + rg * 8 + 2 * p;
        *(float4*)&g_A1[(size_t)row * 32 + cg * 4]       = make_float4(lo0, lo1, lo2, lo3);
        *(float4*)&g_A1[(size_t)(row + 1) * 32 + cg * 4] = make_float4(hi0, hi1, hi2, hi3);
    }
}

// ---------------- launch ----------------
extern "C" void kernel_launch(void* const* d_in, const int* in_sizes, int n_in,
                              void* d_out, int out_size) {
    const float* x  = (const float*)d_in[0];    // (T,N,32) f32
    const int*   ei = (const int*)d_in[1];      // (2,E) int32
    const float* ew = (const float*)d_in[2];    // (E,) f32
    // d_in[3] = missing_mask (unused)
    const float* W1 = (const float*)d_in[4];    // (32,64)
    const float* b1 = (const float*)d_in[5];    // (64,)
    const float* W2 = (const float*)d_in[6];    // (64,32)
    const float* b2 = (const float*)d_in[7];    // (32,)
    float* out = (float*)d_out;

    // 1. fused preprocessing (init + degree + scan + fill), persistent w/ grid barriers
    k_pre<<<PRE_BLOCKS, PRE_THREADS>>>(ei, ew);
    // 2. g_A1 = S(x)
    k_agg_in<<<NODE_BLOCKS, 128>>>(x);
    // 3. g_A1 = relu(g_A1 @ W1 + b1) @ W2   (fused, in-place)
    k_gemm_fused<<<R_ / 128, 128>>>(W1, b1, W2);
    // 4. out = S(g_A1) + b2, plus tail-zero blocks
    int main_elems = T_ * N_ * F_;
    int tail = (out_size > main_elems) ? (out_size - main_elems) : 0;
    int tail_blocks = (tail + 127) / 128;
    k_agg_out<<<NODE_BLOCKS + tail_blocks, 128>>>(b2, out, out_size);
}

// round 10
// speedup vs baseline: 1.0413x; 1.0413x over previous
#include <cuda_runtime.h>
#include <cuda_bf16.h>
#include <stdint.h>

// Problem constants (fixed-shape problem)
#define T_ 16
#define N_ 10000
#define F_ 32          // F_IN
#define FH_ 64         // F_H
#define E_ 160000
#define EP_ (E_ + N_)  // edges + self loops
#define R_ (T_ * N_)   // 160000 rows for GEMMs

// ---------------- device scratch (no allocations allowed) ----------------
__device__ __align__(256) float g_deg[N_];
__device__ __align__(256) int   g_cnt[N_];
__device__ __align__(256) int   g_rowptr[N_ + 1];
__device__ __align__(256) int   g_cursor[N_];
__device__ __align__(256) int   g_srcs[EP_];
__device__ __align__(256) float g_norm[EP_];
__device__ __align__(256) float g_A1[(size_t)R_ * F_];   // 20MB: S(x); rewritten in-place to H@W2

// ---------------- f32x2 helpers ----------------
__device__ __forceinline__ void fma2(uint64_t& d, uint64_t a, uint64_t b) {
    asm("fma.rn.f32x2 %0, %1, %2, %0;" : "+l"(d) : "l"(a), "l"(b));
}
__device__ __forceinline__ uint64_t pk(float lo, float hi) {
    uint64_t r; asm("mov.b64 %0, {%1,%2};" : "=l"(r) : "f"(lo), "f"(hi)); return r;
}
__device__ __forceinline__ void upk(uint64_t v, float& lo, float& hi) {
    asm("mov.b64 {%0,%1}, %2;" : "=f"(lo), "=f"(hi) : "l"(v));
}

// ---------------- init ----------------
__global__ void k_init() {
    int i = blockIdx.x * blockDim.x + threadIdx.x;
    if (i < N_) { g_deg[i] = 0.f; g_cnt[i] = 0; }
}

// ---------------- degree + count histogram, 4 edges/thread (vectorized) ----------------
#define NV_ (E_ / 4)     // 40000 vector-edge threads
#define NSL_ (N_ / 4)    // 2500 self-loop threads
__global__ void k_degree(const int* __restrict__ ei, const float* __restrict__ ew) {
    int i = blockIdx.x * blockDim.x + threadIdx.x;
    if (i < NV_) {
        int4   d4 = ((const int4*)(ei + E_))[i];
        float4 w4 = ((const float4*)ew)[i];
        if ((unsigned)d4.x < N_) { atomicAdd(&g_deg[d4.x], w4.x); atomicAdd(&g_cnt[d4.x], 1); }
        if ((unsigned)d4.y < N_) { atomicAdd(&g_deg[d4.y], w4.y); atomicAdd(&g_cnt[d4.y], 1); }
        if ((unsigned)d4.z < N_) { atomicAdd(&g_deg[d4.z], w4.z); atomicAdd(&g_cnt[d4.z], 1); }
        if ((unsigned)d4.w < N_) { atomicAdd(&g_deg[d4.w], w4.w); atomicAdd(&g_cnt[d4.w], 1); }
    } else {
        int j = i - NV_;
        if (j < NSL_) {
            int base = j * 4;
            #pragma unroll
            for (int r = 0; r < 4; r++) {
                atomicAdd(&g_deg[base + r], 1.f);
                atomicAdd(&g_cnt[base + r], 1);
            }
        }
    }
}

// ---------------- single-block exclusive scan over counts ----------------
__global__ void k_scan() {
    __shared__ int warp_sums[32];
    __shared__ int s_carry;
    int tid = threadIdx.x, lane = tid & 31, wid = tid >> 5;
    if (tid == 0) { s_carry = 0; g_rowptr[0] = 0; }
    __syncthreads();
    for (int base = 0; base < N_; base += 1024) {
        int i = base + tid;
        int v = (i < N_) ? g_cnt[i] : 0;
        int x = v;
        #pragma unroll
        for (int o = 1; o < 32; o <<= 1) {
            int y = __shfl_up_sync(0xffffffffu, x, o);
            if (lane >= o) x += y;
        }
        if (lane == 31) warp_sums[wid] = x;
        __syncthreads();
        if (wid == 0) {
            int s = warp_sums[lane];
            #pragma unroll
            for (int o = 1; o < 32; o <<= 1) {
                int y = __shfl_up_sync(0xffffffffu, s, o);
                if (lane >= o) s += y;
            }
            warp_sums[lane] = s;
        }
        __syncthreads();
        int incl = x + (wid > 0 ? warp_sums[wid - 1] : 0) + s_carry;
        if (i < N_) {
            g_rowptr[i + 1] = incl;
            g_cursor[i]     = incl - v;
        }
        __syncthreads();
        if (tid == 1023) s_carry = incl;
        __syncthreads();
    }
}

// ---------------- fill CSR buckets with (src, norm), 1 edge/thread (max occupancy) ----------------
__global__ void k_fill(const int* __restrict__ ei, const float* __restrict__ ew) {
    int i = blockIdx.x * blockDim.x + threadIdx.x;
    if (i >= EP_) return;
    int s, d; float w;
    if (i < E_) { s = ei[i]; d = ei[E_ + i]; w = ew[i]; }
    else        { s = i - E_; d = s;         w = 1.f;   }
    if ((unsigned)s >= N_ || (unsigned)d >= N_) return;
    float degs = g_deg[s], degd = g_deg[d];
    float ds = (degs > 0.f) ? rsqrtf(degs) : 0.f;
    float dd = (degd > 0.f) ? rsqrtf(degd) : 0.f;
    int pos = atomicAdd(&g_cursor[d], 1);
    g_srcs[pos] = s;
    g_norm[pos] = ds * w * dd;
}

// ---------------- aggregation: 2 warps per node (t-halves), float4 lanes ----------------
// warp w -> node n = w>>1, half h = w&1. lane = tg*8+fq; lane covers t = h*8+tg*2+{0,1},
// features fq*4..fq*4+3. 2 float4 accumulators/lane -> low regs, 20000 warps.
#define AGG_WARPS (2 * N_)
#define AGG_BLOCKS ((AGG_WARPS * 32) / 128)   // 5000
__device__ __forceinline__ float4 fma4(float w, float4 v, float4 a) {
    a.x = fmaf(w, v.x, a.x); a.y = fmaf(w, v.y, a.y);
    a.z = fmaf(w, v.z, a.z); a.w = fmaf(w, v.w, a.w);
    return a;
}

__global__ __launch_bounds__(128) void k_agg_in(const float* __restrict__ in) {
    int gw = (blockIdx.x * blockDim.x + threadIdx.x) >> 5;
    if (gw >= AGG_WARPS) return;
    int n = gw >> 1, h = gw & 1;
    int lane = threadIdx.x & 31, tg = lane >> 3, fq = lane & 7;
    int t0 = h * 8 + tg * 2;
    int beg = g_rowptr[n], end = g_rowptr[n + 1];
    const float4* in4 = (const float4*)in;
    const size_t ts = (size_t)N_ * 8;
    const float4* pt0 = in4 + (size_t)t0 * ts + fq;
    const float4* pt1 = pt0 + ts;
    float4 a0 = make_float4(0.f, 0.f, 0.f, 0.f);
    float4 a1 = make_float4(0.f, 0.f, 0.f, 0.f);
    int e = beg;
    for (; e + 1 < end; e += 2) {
        int s0 = g_srcs[e], s1 = g_srcs[e + 1];
        float w0 = g_norm[e], w1 = g_norm[e + 1];
        float4 u0 = __ldg(pt0 + (size_t)s0 * 8);
        float4 u1 = __ldg(pt1 + (size_t)s0 * 8);
        float4 v0 = __ldg(pt0 + (size_t)s1 * 8);
        float4 v1 = __ldg(pt1 + (size_t)s1 * 8);
        a0 = fma4(w0, u0, a0); a1 = fma4(w0, u1, a1);
        a0 = fma4(w1, v0, a0); a1 = fma4(w1, v1, a1);
    }
    if (e < end) {
        int s0 = g_srcs[e]; float w0 = g_norm[e];
        a0 = fma4(w0, __ldg(pt0 + (size_t)s0 * 8), a0);
        a1 = fma4(w0, __ldg(pt1 + (size_t)s0 * 8), a1);
    }
    float4* o4 = (float4*)g_A1;
    o4[(size_t)t0 * ts + (size_t)n * 8 + fq]       = a0;
    o4[(size_t)(t0 + 1) * ts + (size_t)n * 8 + fq] = a1;
}

// agg_out with fused tail-zero: blocks [0, AGG_BLOCKS) do nodes; rest zero the tail.
__global__ __launch_bounds__(128) void k_agg_out(const float* __restrict__ bias,
                                                 float* __restrict__ out, int out_size) {
    if (blockIdx.x >= AGG_BLOCKS) {
        int main_elems = T_ * N_ * F_;
        int i = main_elems + (blockIdx.x - AGG_BLOCKS) * 128 + threadIdx.x;
        if (i < out_size) out[i] = 0.f;
        return;
    }
    int gw = (blockIdx.x * blockDim.x + threadIdx.x) >> 5;
    int n = gw >> 1, h = gw & 1;
    int lane = threadIdx.x & 31, tg = lane >> 3, fq = lane & 7;
    int t0 = h * 8 + tg * 2;
    int beg = g_rowptr[n], end = g_rowptr[n + 1];
    const float4* in4 = (const float4*)g_A1;
    const size_t ts = (size_t)N_ * 8;
    const float4* pt0 = in4 + (size_t)t0 * ts + fq;
    const float4* pt1 = pt0 + ts;
    float4 a0 = make_float4(0.f, 0.f, 0.f, 0.f);
    float4 a1 = make_float4(0.f, 0.f, 0.f, 0.f);
    int e = beg;
    for (; e + 1 < end; e += 2) {
        int s0 = g_srcs[e], s1 = g_srcs[e + 1];
        float w0 = g_norm[e], w1 = g_norm[e + 1];
        float4 u0 = pt0[(size_t)s0 * 8];
        float4 u1 = pt1[(size_t)s0 * 8];
        float4 v0 = pt0[(size_t)s1 * 8];
        float4 v1 = pt1[(size_t)s1 * 8];
        a0 = fma4(w0, u0, a0); a1 = fma4(w0, u1, a1);
        a0 = fma4(w1, v0, a0); a1 = fma4(w1, v1, a1);
    }
    if (e < end) {
        int s0 = g_srcs[e]; float w0 = g_norm[e];
        a0 = fma4(w0, pt0[(size_t)s0 * 8], a0);
        a1 = fma4(w0, pt1[(size_t)s0 * 8], a1);
    }
    float4 b = ((const float4*)bias)[fq];
    a0.x += b.x; a0.y += b.y; a0.z += b.z; a0.w += b.w;
    a1.x += b.x; a1.y += b.y; a1.z += b.z; a1.w += b.w;
    float4* o4 = (float4*)out;
    o4[(size_t)t0 * ts + (size_t)n * 8 + fq]       = a0;
    o4[(size_t)(t0 + 1) * ts + (size_t)n * 8 + fq] = a1;
}

// ---------------- fused GEMM: g_A1 <- relu(g_A1 @ W1 + b1) @ W2  (in-place, 128-row tiles)
__global__ __launch_bounds__(128) void k_gemm_fused(const float* __restrict__ W1,
                                                    const float* __restrict__ b1,
                                                    const float* __restrict__ W2) {
    __shared__ float S[12288];     // 48KB
    float* U   = S;                // [0,4096):  stage1 As k-major; stage2 Wd2
    float* Wd1 = S + 4096;         // [4096,8192): W1 dup (stage1 only)
    float* Hs  = S + 4096;         // [4096,12288): H k-major (after stage1)
    int tid = threadIdx.x;
    int r0 = blockIdx.x * 128;

    // ---- phase 1: load A tile (transpose to k-major, swizzled) + Wd1 ----
    {
        const float4* A4 = (const float4*)(g_A1 + (size_t)r0 * 32);
        #pragma unroll
        for (int it = 0; it < 8; it++) {
            int idx = it * 128 + tid;      // 0..1023
            int row = idx >> 3, c4 = idx & 7;
            float4 v = A4[idx];
            int k0 = c4 * 4;
            int sw = c4 * 4;               // sigmaA(k) = (k>>2)*4
            U[(k0 + 0) * 128 + (row ^ sw)] = v.x;
            U[(k0 + 1) * 128 + (row ^ sw)] = v.y;
            U[(k0 + 2) * 128 + (row ^ sw)] = v.z;
            U[(k0 + 3) * 128 + (row ^ sw)] = v.w;
        }
        #pragma unroll
        for (int it = 0; it < 16; it++) {
            int idx = it * 128 + tid;      // 0..2047
            int k = idx >> 6, c = idx & 63;
            float w = W1[idx];
            int off = k * 128 + (c & 7) * 16 + (c >> 3) * 2;
            Wd1[off] = w; Wd1[off + 1] = w;
        }
    }
    __syncthreads();

    // ---- stage 1: H(128x64) = A(128x32) @ W1(32x64) ----
    int rg = tid >> 3, cg = tid & 7;
    uint64_t acc[4][8];
    #pragma unroll
    for (int p = 0; p < 4; p++)
        #pragma unroll
        for (int j = 0; j < 8; j++) acc[p][j] = 0ull;

    #pragma unroll
    for (int k = 0; k < 32; k++) {
        int sw = (k >> 2) * 4;
        uint64_t a2[4], b2[8];
        #pragma unroll
        for (int p = 0; p < 4; p++)
            a2[p] = *(const uint64_t*)&U[k * 128 + ((rg * 8 + 2 * p) ^ sw)];
        #pragma unroll
        for (int j = 0; j < 8; j++)
            b2[j] = *(const uint64_t*)&Wd1[k * 128 + j * 16 + cg * 2];
        #pragma unroll
        for (int p = 0; p < 4; p++)
            #pragma unroll
            for (int j = 0; j < 8; j++)
                fma2(acc[p][j], a2[p], b2[j]);
    }
    __syncthreads();

    // ---- phase 3: load Wd2 into U; write H (bias+relu) to Hs ----
    #pragma unroll
    for (int it = 0; it < 16; it++) {
        int idx = it * 128 + tid;
        int k = idx >> 5, c = idx & 31;
        float w = W2[idx];
        int off = k * 64 + (c & 3) * 16 + (c >> 2) * 2;
        U[off] = w; U[off + 1] = w;
    }
    {
        int q = cg;
        int sh = (q & 3) * 4 + (q >> 2) * 2;
        #pragma unroll
        for (int j = 0; j < 8; j++) {
            int c = cg * 8 + j;
            float bc = b1[c];
            #pragma unroll
            for (int p = 0; p < 4; p++) {
                float lo, hi; upk(acc[p][j], lo, hi);
                lo = fmaxf(lo + bc, 0.f);
                hi = fmaxf(hi + bc, 0.f);
                *(uint64_t*)&Hs[c * 128 + ((rg * 8 + 2 * p) ^ sh)] = pk(lo, hi);
            }
        }
    }
    __syncthreads();

    // ---- stage 2: Out(128x32) = H(128x64) @ W2(64x32) ----
    uint64_t acc2[4][4];
    #pragma unroll
    for (int p = 0; p < 4; p++)
        #pragma unroll
        for (int j = 0; j < 4; j++) acc2[p][j] = 0ull;

    #pragma unroll
    for (int k = 0; k < 64; k++) {
        int q = k >> 3;
        int sh = (q & 3) * 4 + (q >> 2) * 2;
        uint64_t a2[4], b2[4];
        #pragma unroll
        for (int p = 0; p < 4; p++)
            a2[p] = *(const uint64_t*)&Hs[k * 128 + ((rg * 8 + 2 * p) ^ sh)];
        #pragma unroll
        for (int j = 0; j < 4; j++)
            b2[j] = *(const uint64_t*)&U[k * 64 + j * 16 + cg * 2];
        #pragma unroll
        for (int p = 0; p < 4; p++)
            #pragma unroll
            for (int j = 0; j < 4; j++)
                fma2(acc2[p][j], a2[p], b2[j]);
    }

    // ---- epilogue: write back in-place ----
    #pragma unroll
    for (int p = 0; p < 4; p++) {
        float lo0, hi0, lo1, hi1, lo2, hi2, lo3, hi3;
        upk(acc2[p][0], lo0, hi0);
        upk(acc2[p][1], lo1, hi1);
        upk(acc2[p][2], lo2, hi2);
        upk(acc2[p][3], lo3, hi3);
        int row = r0 + rg * 8 + 2 * p;
        *(float4*)&g_A1[(size_t)row * 32 + cg * 4]       = make_float4(lo0, lo1, lo2, lo3);
        *(float4*)&g_A1[(size_t)(row + 1) * 32 + cg * 4] = make_float4(hi0, hi1, hi2, hi3);
    }
}

// ---------------- launch ----------------
extern "C" void kernel_launch(void* const* d_in, const int* in_sizes, int n_in,
                              void* d_out, int out_size) {
    const float* x  = (const float*)d_in[0];    // (T,N,32) f32
    const int*   ei = (const int*)d_in[1];      // (2,E) int32
    const float* ew = (const float*)d_in[2];    // (E,) f32
    // d_in[3] = missing_mask (unused)
    const float* W1 = (const float*)d_in[4];    // (32,64)
    const float* b1 = (const float*)d_in[5];    // (64,)
    const float* W2 = (const float*)d_in[6];    // (64,32)
    const float* b2 = (const float*)d_in[7];    // (32,)
    float* out = (float*)d_out;

    k_init<<<(N_ + 255) / 256, 256>>>();
    k_degree<<<(NV_ + NSL_ + 255) / 256, 256>>>(ei, ew);
    k_scan<<<1, 1024>>>();
    k_fill<<<(EP_ + 255) / 256, 256>>>(ei, ew);
    // g_A1 = S(x)
    k_agg_in<<<AGG_BLOCKS, 128>>>(x);
    // g_A1 = relu(g_A1 @ W1 + b1) @ W2   (fused, in-place)
    k_gemm_fused<<<R_ / 128, 128>>>(W1, b1, W2);
    // out = S(g_A1) + b2, plus tail-zero blocks
    int main_elems = T_ * N_ * F_;
    int tail = (out_size > main_elems) ? (out_size - main_elems) : 0;
    int tail_blocks = (tail + 127) / 128;
    k_agg_out<<<AGG_BLOCKS + tail_blocks, 128>>>(b2, out, out_size);
}

// round 12
// speedup vs baseline: 1.0821x; 1.0392x over previous
#include <cuda_runtime.h>
#include <cuda_bf16.h>
#include <stdint.h>

// Problem constants (fixed-shape problem)
#define T_ 16
#define N_ 10000
#define F_ 32          // F_IN
#define FH_ 64         // F_H
#define E_ 160000
#define EP_ (E_ + N_)  // edges + self loops
#define R_ (T_ * N_)   // 160000 rows for GEMMs

// ---------------- device scratch (no allocations allowed) ----------------
// g_degcnt: cnt in bits [40,64), deg fixed-point (x 2^23) in bits [0,40).
// Zeroed at the END of each call (extra blocks in k_agg_out) so the next
// replay starts clean; zero-initialized at module load for the first call.
__device__ __align__(256) unsigned long long g_degcnt[N_];
__device__ __align__(256) float g_dis[N_];
__device__ __align__(256) int   g_rowptr[N_ + 1];
__device__ __align__(256) int   g_cursor[N_];
__device__ __align__(256) long long g_edge[EP_];          // packed (norm<<32 | src)
__device__ __align__(256) float g_A1[(size_t)R_ * F_];    // 20MB: S(x); rewritten in-place to H@W2

#define FIX_SCALE 8388608.0f          // 2^23
#define FIX_INV   (1.0f / 8388608.0f)
#define MASK40    ((1ull << 40) - 1)

// ---------------- f32x2 helpers ----------------
__device__ __forceinline__ void fma2(uint64_t& d, uint64_t a, uint64_t b) {
    asm("fma.rn.f32x2 %0, %1, %2, %0;" : "+l"(d) : "l"(a), "l"(b));
}
__device__ __forceinline__ uint64_t pk(float lo, float hi) {
    uint64_t r; asm("mov.b64 %0, {%1,%2};" : "=l"(r) : "f"(lo), "f"(hi)); return r;
}
__device__ __forceinline__ void upk(uint64_t v, float& lo, float& hi) {
    asm("mov.b64 {%0,%1}, %2;" : "=f"(lo), "=f"(hi) : "l"(v));
}

// ---------------- degree + count histogram, 2 edges/thread, ONE 64b atomic each ----------------
#define NV2_ (E_ / 2)     // 80000 vector-edge threads
#define NSL2_ (N_ / 2)    // 5000 self-loop threads
__global__ void k_degree(const int* __restrict__ ei, const float* __restrict__ ew) {
    int i = blockIdx.x * blockDim.x + threadIdx.x;
    if (i < NV2_) {
        int2   d2 = ((const int2*)(ei + E_))[i];
        float2 w2 = ((const float2*)ew)[i];
        if ((unsigned)d2.x < N_)
            atomicAdd(&g_degcnt[d2.x], (1ull << 40) | (unsigned long long)__float2uint_rn(w2.x * FIX_SCALE));
        if ((unsigned)d2.y < N_)
            atomicAdd(&g_degcnt[d2.y], (1ull << 40) | (unsigned long long)__float2uint_rn(w2.y * FIX_SCALE));
    } else {
        int j = i - NV2_;
        if (j < NSL2_) {
            const unsigned long long one = (1ull << 40) | (1ull << 23);
            atomicAdd(&g_degcnt[j * 2],     one);
            atomicAdd(&g_degcnt[j * 2 + 1], one);
        }
    }
}

// ---------------- single-block scan: unpack degcnt -> rowptr/cursor + dis ----------------
__global__ void k_scan() {
    __shared__ int warp_sums[32];
    __shared__ int s_carry;
    int tid = threadIdx.x, lane = tid & 31, wid = tid >> 5;
    if (tid == 0) { s_carry = 0; g_rowptr[0] = 0; }
    __syncthreads();
    for (int base = 0; base < N_; base += 1024) {
        int i = base + tid;
        int v = 0;
        if (i < N_) {
            unsigned long long dc = g_degcnt[i];
            v = (int)(dc >> 40);
            unsigned long long low = dc & MASK40;
            float deg = (float)low * FIX_INV;
            g_dis[i] = (low > 0) ? rsqrtf(deg) : 0.f;
        }
        int x = v;
        #pragma unroll
        for (int o = 1; o < 32; o <<= 1) {
            int y = __shfl_up_sync(0xffffffffu, x, o);
            if (lane >= o) x += y;
        }
        if (lane == 31) warp_sums[wid] = x;
        __syncthreads();
        if (wid == 0) {
            int s = warp_sums[lane];
            #pragma unroll
            for (int o = 1; o < 32; o <<= 1) {
                int y = __shfl_up_sync(0xffffffffu, s, o);
                if (lane >= o) s += y;
            }
            warp_sums[lane] = s;
        }
        __syncthreads();
        int incl = x + (wid > 0 ? warp_sums[wid - 1] : 0) + s_carry;
        if (i < N_) {
            g_rowptr[i + 1] = incl;
            g_cursor[i]     = incl - v;
        }
        __syncthreads();
        if (tid == 1023) s_carry = incl;
        __syncthreads();
    }
}

// ---------------- fill CSR buckets with packed (src, norm), 1 edge/thread ----------------
__global__ void k_fill(const int* __restrict__ ei, const float* __restrict__ ew) {
    int i = blockIdx.x * blockDim.x + threadIdx.x;
    if (i >= EP_) return;
    int s, d; float w;
    if (i < E_) { s = ei[i]; d = ei[E_ + i]; w = ew[i]; }
    else        { s = i - E_; d = s;         w = 1.f;   }
    if ((unsigned)s >= N_ || (unsigned)d >= N_) return;
    float norm = g_dis[s] * w * g_dis[d];
    int pos = atomicAdd(&g_cursor[d], 1);
    g_edge[pos] = ((long long)__float_as_int(norm) << 32) | (unsigned int)s;
}

// ---------------- aggregation: 2 warps per node (t-halves), 4-edge unroll ----------------
#define AGG_WARPS (2 * N_)
#define AGG_BLOCKS ((AGG_WARPS * 32) / 128)   // 5000
#define DZ_BLOCKS ((N_ + 127) / 128)          // 79: zero g_degcnt at end of call
__device__ __forceinline__ float4 fma4(float w, float4 v, float4 a) {
    a.x = fmaf(w, v.x, a.x); a.y = fmaf(w, v.y, a.y);
    a.z = fmaf(w, v.z, a.z); a.w = fmaf(w, v.w, a.w);
    return a;
}
__device__ __forceinline__ void unpack_edge(long long pe, int& s, float& w) {
    s = (int)(unsigned int)(pe & 0xffffffffll);
    w = __int_as_float((int)(pe >> 32));
}

__global__ __launch_bounds__(128) void k_agg_in(const float* __restrict__ in) {
    int gw = (blockIdx.x * blockDim.x + threadIdx.x) >> 5;
    if (gw >= AGG_WARPS) return;
    int n = gw >> 1, h = gw & 1;
    int lane = threadIdx.x & 31, tg = lane >> 3, fq = lane & 7;
    int t0 = h * 8 + tg * 2;
    int beg = g_rowptr[n], end = g_rowptr[n + 1];
    const float4* in4 = (const float4*)in;
    const size_t ts = (size_t)N_ * 8;
    const float4* pt0 = in4 + (size_t)t0 * ts + fq;
    const float4* pt1 = pt0 + ts;
    float4 a0 = make_float4(0.f, 0.f, 0.f, 0.f);
    float4 a1 = make_float4(0.f, 0.f, 0.f, 0.f);
    int e = beg;
    for (; e + 3 < end; e += 4) {
        int s0, s1, s2, s3; float w0, w1, w2, w3;
        unpack_edge(g_edge[e],     s0, w0);
        unpack_edge(g_edge[e + 1], s1, w1);
        unpack_edge(g_edge[e + 2], s2, w2);
        unpack_edge(g_edge[e + 3], s3, w3);
        float4 u0 = __ldg(pt0 + (size_t)s0 * 8), u1 = __ldg(pt1 + (size_t)s0 * 8);
        float4 u2 = __ldg(pt0 + (size_t)s1 * 8), u3 = __ldg(pt1 + (size_t)s1 * 8);
        float4 u4 = __ldg(pt0 + (size_t)s2 * 8), u5 = __ldg(pt1 + (size_t)s2 * 8);
        float4 u6 = __ldg(pt0 + (size_t)s3 * 8), u7 = __ldg(pt1 + (size_t)s3 * 8);
        a0 = fma4(w0, u0, a0); a1 = fma4(w0, u1, a1);
        a0 = fma4(w1, u2, a0); a1 = fma4(w1, u3, a1);
        a0 = fma4(w2, u4, a0); a1 = fma4(w2, u5, a1);
        a0 = fma4(w3, u6, a0); a1 = fma4(w3, u7, a1);
    }
    for (; e < end; e++) {
        int s0; float w0; unpack_edge(g_edge[e], s0, w0);
        a0 = fma4(w0, __ldg(pt0 + (size_t)s0 * 8), a0);
        a1 = fma4(w0, __ldg(pt1 + (size_t)s0 * 8), a1);
    }
    float4* o4 = (float4*)g_A1;
    o4[(size_t)t0 * ts + (size_t)n * 8 + fq]       = a0;
    o4[(size_t)(t0 + 1) * ts + (size_t)n * 8 + fq] = a1;
}

// agg_out: blocks [0,AGG_BLOCKS) aggregate; next DZ_BLOCKS zero g_degcnt; rest zero tail.
__global__ __launch_bounds__(128) void k_agg_out(const float* __restrict__ bias,
                                                 float* __restrict__ out, int out_size) {
    if (blockIdx.x >= AGG_BLOCKS) {
        int zb = blockIdx.x - AGG_BLOCKS;
        if (zb < DZ_BLOCKS) {
            int i = zb * 128 + threadIdx.x;
            if (i < N_) g_degcnt[i] = 0ull;
        } else {
            int main_elems = T_ * N_ * F_;
            int i = main_elems + (zb - DZ_BLOCKS) * 128 + threadIdx.x;
            if (i < out_size) out[i] = 0.f;
        }
        return;
    }
    int gw = (blockIdx.x * blockDim.x + threadIdx.x) >> 5;
    int n = gw >> 1, h = gw & 1;
    int lane = threadIdx.x & 31, tg = lane >> 3, fq = lane & 7;
    int t0 = h * 8 + tg * 2;
    int beg = g_rowptr[n], end = g_rowptr[n + 1];
    const float4* in4 = (const float4*)g_A1;
    const size_t ts = (size_t)N_ * 8;
    const float4* pt0 = in4 + (size_t)t0 * ts + fq;
    const float4* pt1 = pt0 + ts;
    float4 a0 = make_float4(0.f, 0.f, 0.f, 0.f);
    float4 a1 = make_float4(0.f, 0.f, 0.f, 0.f);
    int e = beg;
    for (; e + 3 < end; e += 4) {
        int s0, s1, s2, s3; float w0, w1, w2, w3;
        unpack_edge(g_edge[e],     s0, w0);
        unpack_edge(g_edge[e + 1], s1, w1);
        unpack_edge(g_edge[e + 2], s2, w2);
        unpack_edge(g_edge[e + 3], s3, w3);
        float4 u0 = pt0[(size_t)s0 * 8], u1 = pt1[(size_t)s0 * 8];
        float4 u2 = pt0[(size_t)s1 * 8], u3 = pt1[(size_t)s1 * 8];
        float4 u4 = pt0[(size_t)s2 * 8], u5 = pt1[(size_t)s2 * 8];
        float4 u6 = pt0[(size_t)s3 * 8], u7 = pt1[(size_t)s3 * 8];
        a0 = fma4(w0, u0, a0); a1 = fma4(w0, u1, a1);
        a0 = fma4(w1, u2, a0); a1 = fma4(w1, u3, a1);
        a0 = fma4(w2, u4, a0); a1 = fma4(w2, u5, a1);
        a0 = fma4(w3, u6, a0); a1 = fma4(w3, u7, a1);
    }
    for (; e < end; e++) {
        int s0; float w0; unpack_edge(g_edge[e], s0, w0);
        a0 = fma4(w0, pt0[(size_t)s0 * 8], a0);
        a1 = fma4(w0, pt1[(size_t)s0 * 8], a1);
    }
    float4 b = ((const float4*)bias)[fq];
    a0.x += b.x; a0.y += b.y; a0.z += b.z; a0.w += b.w;
    a1.x += b.x; a1.y += b.y; a1.z += b.z; a1.w += b.w;
    float4* o4 = (float4*)out;
    o4[(size_t)t0 * ts + (size_t)n * 8 + fq]       = a0;
    o4[(size_t)(t0 + 1) * ts + (size_t)n * 8 + fq] = a1;
}

// ---------------- fused GEMM: g_A1 <- relu(g_A1 @ W1 + b1) @ W2  (in-place, 128-row tiles)
__global__ __launch_bounds__(128) void k_gemm_fused(const float* __restrict__ W1,
                                                    const float* __restrict__ b1,
                                                    const float* __restrict__ W2) {
    __shared__ float S[12288];     // 48KB
    float* U   = S;                // [0,4096):  stage1 As k-major; stage2 Wd2
    float* Wd1 = S + 4096;         // [4096,8192): W1 dup (stage1 only)
    float* Hs  = S + 4096;         // [4096,12288): H k-major (after stage1)
    int tid = threadIdx.x;
    int r0 = blockIdx.x * 128;

    // ---- phase 1: load A tile (transpose to k-major, swizzled) + Wd1 ----
    {
        const float4* A4 = (const float4*)(g_A1 + (size_t)r0 * 32);
        #pragma unroll
        for (int it = 0; it < 8; it++) {
            int idx = it * 128 + tid;      // 0..1023
            int row = idx >> 3, c4 = idx & 7;
            float4 v = A4[idx];
            int k0 = c4 * 4;
            int sw = c4 * 4;               // sigmaA(k) = (k>>2)*4
            U[(k0 + 0) * 128 + (row ^ sw)] = v.x;
            U[(k0 + 1) * 128 + (row ^ sw)] = v.y;
            U[(k0 + 2) * 128 + (row ^ sw)] = v.z;
            U[(k0 + 3) * 128 + (row ^ sw)] = v.w;
        }
        #pragma unroll
        for (int it = 0; it < 16; it++) {
            int idx = it * 128 + tid;      // 0..2047
            int k = idx >> 6, c = idx & 63;
            float w = W1[idx];
            int off = k * 128 + (c & 7) * 16 + (c >> 3) * 2;
            Wd1[off] = w; Wd1[off + 1] = w;
        }
    }
    __syncthreads();

    // ---- stage 1: H(128x64) = A(128x32) @ W1(32x64) ----
    int rg = tid >> 3, cg = tid & 7;
    uint64_t acc[4][8];
    #pragma unroll
    for (int p = 0; p < 4; p++)
        #pragma unroll
        for (int j = 0; j < 8; j++) acc[p][j] = 0ull;

    #pragma unroll
    for (int k = 0; k < 32; k++) {
        int sw = (k >> 2) * 4;
        uint64_t a2[4], b2[8];
        #pragma unroll
        for (int p = 0; p < 4; p++)
            a2[p] = *(const uint64_t*)&U[k * 128 + ((rg * 8 + 2 * p) ^ sw)];
        #pragma unroll
        for (int j = 0; j < 8; j++)
            b2[j] = *(const uint64_t*)&Wd1[k * 128 + j * 16 + cg * 2];
        #pragma unroll
        for (int p = 0; p < 4; p++)
            #pragma unroll
            for (int j = 0; j < 8; j++)
                fma2(acc[p][j], a2[p], b2[j]);
    }
    __syncthreads();

    // ---- phase 3: load Wd2 into U; write H (bias+relu) to Hs ----
    #pragma unroll
    for (int it = 0; it < 16; it++) {
        int idx = it * 128 + tid;
        int k = idx >> 5, c = idx & 31;
        float w = W2[idx];
        int off = k * 64 + (c & 3) * 16 + (c >> 2) * 2;
        U[off] = w; U[off + 1] = w;
    }
    {
        int q = cg;
        int sh = (q & 3) * 4 + (q >> 2) * 2;
        #pragma unroll
        for (int j = 0; j < 8; j++) {
            int c = cg * 8 + j;
            float bc = b1[c];
            #pragma unroll
            for (int p = 0; p < 4; p++) {
                float lo, hi; upk(acc[p][j], lo, hi);
                lo = fmaxf(lo + bc, 0.f);
                hi = fmaxf(hi + bc, 0.f);
                *(uint64_t*)&Hs[c * 128 + ((rg * 8 + 2 * p) ^ sh)] = pk(lo, hi);
            }
        }
    }
    __syncthreads();

    // ---- stage 2: Out(128x32) = H(128x64) @ W2(64x32) ----
    uint64_t acc2[4][4];
    #pragma unroll
    for (int p = 0; p < 4; p++)
        #pragma unroll
        for (int j = 0; j < 4; j++) acc2[p][j] = 0ull;

    #pragma unroll
    for (int k = 0; k < 64; k++) {
        int q = k >> 3;
        int sh = (q & 3) * 4 + (q >> 2) * 2;
        uint64_t a2[4], b2[4];
        #pragma unroll
        for (int p = 0; p < 4; p++)
            a2[p] = *(const uint64_t*)&Hs[k * 128 + ((rg * 8 + 2 * p) ^ sh)];
        #pragma unroll
        for (int j = 0; j < 4; j++)
            b2[j] = *(const uint64_t*)&U[k * 64 + j * 16 + cg * 2];
        #pragma unroll
        for (int p = 0; p < 4; p++)
            #pragma unroll
            for (int j = 0; j < 4; j++)
                fma2(acc2[p][j], a2[p], b2[j]);
    }

    // ---- epilogue: write back in-place ----
    #pragma unroll
    for (int p = 0; p < 4; p++) {
        float lo0, hi0, lo1, hi1, lo2, hi2, lo3, hi3;
        upk(acc2[p][0], lo0, hi0);
        upk(acc2[p][1], lo1, hi1);
        upk(acc2[p][2], lo2, hi2);
        upk(acc2[p][3], lo3, hi3);
        int row = r0 + rg * 8 + 2 * p;
        *(float4*)&g_A1[(size_t)row * 32 + cg * 4]       = make_float4(lo0, lo1, lo2, lo3);
        *(float4*)&g_A1[(size_t)(row + 1) * 32 + cg * 4] = make_float4(hi0, hi1, hi2, hi3);
    }
}

// ---------------- launch ----------------
extern "C" void kernel_launch(void* const* d_in, const int* in_sizes, int n_in,
                              void* d_out, int out_size) {
    const float* x  = (const float*)d_in[0];    // (T,N,32) f32
    const int*   ei = (const int*)d_in[1];      // (2,E) int32
    const float* ew = (const float*)d_in[2];    // (E,) f32
    // d_in[3] = missing_mask (unused)
    const float* W1 = (const float*)d_in[4];    // (32,64)
    const float* b1 = (const float*)d_in[5];    // (64,)
    const float* W2 = (const float*)d_in[6];    // (64,32)
    const float* b2 = (const float*)d_in[7];    // (32,)
    float* out = (float*)d_out;

    // (g_degcnt is zero here: zero-init at load, re-zeroed at end of every call)
    k_degree<<<(NV2_ + NSL2_ + 255) / 256, 256>>>(ei, ew);
    k_scan<<<1, 1024>>>();
    k_fill<<<(EP_ + 255) / 256, 256>>>(ei, ew);
    // g_A1 = S(x)
    k_agg_in<<<AGG_BLOCKS, 128>>>(x);
    // g_A1 = relu(g_A1 @ W1 + b1) @ W2   (fused, in-place)
    k_gemm_fused<<<R_ / 128, 128>>>(W1, b1, W2);
    // out = S(g_A1) + b2, plus degcnt-zero and tail-zero blocks
    int main_elems = T_ * N_ * F_;
    int tail = (out_size > main_elems) ? (out_size - main_elems) : 0;
    int tail_blocks = (tail + 127) / 128;
    k_agg_out<<<AGG_BLOCKS + DZ_BLOCKS + tail_blocks, 128>>>(b2, out, out_size);
}